// round 8
// baseline (speedup 1.0000x reference)
#include <cuda_runtime.h>

// Problem constants
#define NPTS     8193            // positions per chain (incl. leading zero row)
#define NCHAIN   2
#define CONFLEN  16388

// Chunking: 32-point tiles, one warp per tile pair
#define CHUNK    32
#define NCHUNK   257                             // ceil(8193/32)
#define PADN     (NCHUNK * CHUNK)                // 8224
#define NPAIR    (NCHUNK * (NCHUNK + 1) / 2)     // 33153 (cj >= ci)
#define MAXITEMS (NPAIR * NCHAIN)

#define PBLOCK   512
#define PGRID    296
#define NWARPS   (PGRID * (PBLOCK / 32))         // 4736

// Scaled-space cutoff: dropped pair value <= 2^(-0.5*64) = 2.3e-10
#define DCUT_HAT 8.0f

// Fixed-point scale for deterministic integer accumulation
#define FXSCALE  16777216.0f     // 2^24

// Scratch (no allocations allowed; zero-initialized at load)
__device__ float4 g_pts[NCHAIN][PADN];           // (x_hat, y_hat, z_hat, a)
__device__ int    g_live[MAXITEMS];              // packed live items
__device__ unsigned int g_live_cnt;
__device__ unsigned int g_ready;                 // chains finished setup+plan
__device__ unsigned long long g_acc;             // fixed-point sum
__device__ unsigned int g_count;                 // finished-block counter

__global__ void __launch_bounds__(PBLOCK, 2)
fused_kernel(const float* __restrict__ conf, float* __restrict__ out) {
    const int tid = threadIdx.x;
    const int lane = tid & 31;
    const int warp = tid >> 5;

    // =====================================================================
    // Phase 1: blocks 0..NCHAIN-1 build their chain + plan live tile pairs.
    // =====================================================================
    if (blockIdx.x < NCHAIN) {
        const int chain = blockIdx.x;
        const float2* cp = (const float2*)(conf + chain * CONFLEN + 4);
        const float TWO_PI = 6.2831853071795864769f;

        // pass 1: 16 steps per thread, raw local prefix staged in g_pts
        float sx = 0.f, sy = 0.f, sz = 0.f;
        #pragma unroll
        for (int m = 0; m < 16; m++) {
            float2 rr = cp[tid * 16 + m];
            float r1 = rr.x + 0.5f;
            float r2 = rr.y + 0.5f;
            float z  = 1.0f - 2.0f * r2;                   // cos(theta)
            float sth = sqrtf(fmaxf(1.0f - z * z, 0.0f));  // sin(theta)
            float s, c;
            __sincosf(r1 * TWO_PI, &s, &c);
            sx += sth * c;
            sy += sth * s;
            sz += z;
            g_pts[chain][tid * 16 + m + 1] = make_float4(sx, sy, sz, 0.f);
        }

        // block scan of thread totals (16 warps)
        float tx = sx, ty = sy, tz = sz;
        #pragma unroll
        for (int d = 1; d < 32; d <<= 1) {
            float ox = __shfl_up_sync(0xffffffffu, tx, d);
            float oy = __shfl_up_sync(0xffffffffu, ty, d);
            float oz = __shfl_up_sync(0xffffffffu, tz, d);
            if (lane >= d) { tx += ox; ty += oy; tz += oz; }
        }
        __shared__ float3 wtot[16], woff[16];
        __shared__ float4 cb[NCHUNK];
        __shared__ float4 lastpt_s;
        if (lane == 31) wtot[warp] = make_float3(tx, ty, tz);
        __syncthreads();
        if (tid == 0) {
            float ax = 0.f, ay = 0.f, az = 0.f;
            #pragma unroll
            for (int w = 0; w < 16; w++) {
                float3 v = wtot[w];
                woff[w] = make_float3(ax, ay, az);
                ax += v.x; ay += v.y; az += v.z;
            }
        }
        __syncthreads();
        float bx = woff[warp].x + (tx - sx);
        float by = woff[warp].y + (ty - sy);
        float bz = woff[warp].z + (tz - sz);

        // arg = a_i + a_j + dot(p_hat_i, p_hat_j), p_hat = SS*p, a=-0.5|p_hat|^2
        const float S2 = 8.0f * 1.4426950408889634f;   // 8*log2(e)
        const float SS = sqrtf(S2);                    // scaled step length

        // pass 2: finalize points, track per-thread AABB (16 points)
        float mnx = 1e30f, mxx = -1e30f, mny = 1e30f, mxy = -1e30f;
        float mnz = 1e30f, mxz = -1e30f;
        float4 mylast = make_float4(0.f, 0.f, 0.f, 0.f);
        #pragma unroll
        for (int m = 0; m < 16; m++) {
            float4 pr = g_pts[chain][tid * 16 + m + 1];
            float xh = SS * (bx + pr.x);
            float yh = SS * (by + pr.y);
            float zh = SS * (bz + pr.z);
            float a = -0.5f * (xh * xh + yh * yh + zh * zh);
            mylast = make_float4(xh, yh, zh, a);
            g_pts[chain][tid * 16 + m + 1] = mylast;
            mnx = fminf(mnx, xh); mxx = fmaxf(mxx, xh);
            mny = fminf(mny, yh); mxy = fmaxf(mxy, yh);
            mnz = fminf(mnz, zh); mxz = fmaxf(mxz, zh);
        }
        if (tid == 0)   g_pts[chain][0] = make_float4(0.f, 0.f, 0.f, 0.f);
        if (tid == 511) lastpt_s = mylast;   // point 8192

        // chunk bounds: thread pair (2c, 2c+1) covers points [32c+1, 32c+33);
        // +SS inflation covers the boundary point 32c.
        mnx = fminf(mnx, __shfl_xor_sync(0xffffffffu, mnx, 1));
        mxx = fmaxf(mxx, __shfl_xor_sync(0xffffffffu, mxx, 1));
        mny = fminf(mny, __shfl_xor_sync(0xffffffffu, mny, 1));
        mxy = fmaxf(mxy, __shfl_xor_sync(0xffffffffu, mxy, 1));
        mnz = fminf(mnz, __shfl_xor_sync(0xffffffffu, mnz, 1));
        mxz = fmaxf(mxz, __shfl_xor_sync(0xffffffffu, mxz, 1));
        if ((tid & 1) == 0) {
            float hx = 0.5f * (mxx - mnx);
            float hy = 0.5f * (mxy - mny);
            float hz = 0.5f * (mxz - mnz);
            float r = sqrtf(hx * hx + hy * hy + hz * hz) + SS + 1e-2f;
            cb[tid >> 1] = make_float4(0.5f * (mnx + mxx), 0.5f * (mny + mxy),
                                       0.5f * (mnz + mxz), r);
        }
        __syncthreads();
        // chunk 256 = real point 8192 + 31 pads, all at lastpt
        if (tid == 0)
            cb[256] = make_float4(lastpt_s.x, lastpt_s.y, lastpt_s.z, 0.05f);
        // pads: a=-1e30 -> exp2 underflows to exactly 0
        if (tid < PADN - NPTS)
            g_pts[chain][NPTS + tid] =
                make_float4(lastpt_s.x, lastpt_s.y, lastpt_s.z, -1e30f);
        __syncthreads();

        // ---- plan: cull all tile pairs, emit compact live list ----
        for (int p = tid; p < NPAIR; p += PBLOCK) {
            // triangular decode: S(ci) = ci*(2*NCHUNK+1-ci)/2
            float disc = (float)((2 * NCHUNK + 1) * (2 * NCHUNK + 1)) - 8.0f * (float)p;
            int ci = (int)(((float)(2 * NCHUNK + 1) - sqrtf(disc)) * 0.5f);
            if (ci > NCHUNK - 1) ci = NCHUNK - 1;
            while (ci > 0 && (ci * (2 * NCHUNK + 1 - ci)) / 2 > p) ci--;
            while (((ci + 1) * (2 * NCHUNK + 1 - (ci + 1))) / 2 <= p) ci++;
            int cj = ci + (p - (ci * (2 * NCHUNK + 1 - ci)) / 2);

            float4 bi = cb[ci];
            float4 bj = cb[cj];
            float dx = bi.x - bj.x, dy = bi.y - bj.y, dz = bi.z - bj.z;
            float rr = bi.w + bj.w + DCUT_HAT;
            if (dx * dx + dy * dy + dz * dz <= rr * rr) {
                unsigned int idx = atomicAdd(&g_live_cnt, 1u);
                g_live[idx] = (chain << 20) | (ci << 10) | cj;
            }
        }
        __threadfence();
        __syncthreads();
        if (tid == 0) atomicAdd(&g_ready, 1u);
    }

    // =====================================================================
    // Phase 2: all blocks wait for both chains, then warps consume items.
    // Deadlock-free: blocks 0/1 are wave-1 and never wait on other blocks.
    // =====================================================================
    if (tid == 0) {
        while (atomicAdd(&g_ready, 0u) < NCHAIN) __nanosleep(64);
    }
    __syncthreads();
    __threadfence();

    const unsigned int nitems = g_live_cnt;
    const unsigned int gw = blockIdx.x * (PBLOCK / 32) + warp;
    unsigned long long ll = 0ULL;

    for (unsigned int it = gw; it < nitems; it += NWARPS) {
        const int item = g_live[it];
        const int chain = item >> 20;
        const int ci = (item >> 10) & 1023;
        const int cj = item & 1023;

        const float4* __restrict__ jp = &g_pts[chain][cj * CHUNK];
        float4 ip = g_pts[chain][ci * CHUNK + lane];
        float a0 = 0.f, a1 = 0.f;

        if (ci != cj) {
            #pragma unroll
            for (int jj = 0; jj < CHUNK; jj += 2) {
                float4 q0 = jp[jj];
                float4 q1 = jp[jj + 1];
                float m0 = fmaf(ip.x, q0.x, q0.w);
                m0 = fmaf(ip.y, q0.y, m0);
                m0 = fmaf(ip.z, q0.z, m0);
                float m1 = fmaf(ip.x, q1.x, q1.w);
                m1 = fmaf(ip.y, q1.y, m1);
                m1 = fmaf(ip.z, q1.z, m1);
                float e0, e1;
                asm("ex2.approx.f32 %0, %1;" : "=f"(e0) : "f"(m0 + ip.w));
                asm("ex2.approx.f32 %0, %1;" : "=f"(e1) : "f"(m1 + ip.w));
                a0 += e0;
                a1 += e1;
            }
        } else {
            #pragma unroll
            for (int jj = 0; jj < CHUNK; jj += 2) {
                float4 q0 = jp[jj];
                float4 q1 = jp[jj + 1];
                float m0 = fmaf(ip.x, q0.x, q0.w);
                m0 = fmaf(ip.y, q0.y, m0);
                m0 = fmaf(ip.z, q0.z, m0);
                float m1 = fmaf(ip.x, q1.x, q1.w);
                m1 = fmaf(ip.y, q1.y, m1);
                m1 = fmaf(ip.z, q1.z, m1);
                float e0, e1;
                asm("ex2.approx.f32 %0, %1;" : "=f"(e0) : "f"(m0 + ip.w));
                asm("ex2.approx.f32 %0, %1;" : "=f"(e1) : "f"(m1 + ip.w));
                a0 += (jj > lane) ? e0 : 0.f;        // strict upper triangle
                a1 += (jj + 1 > lane) ? e1 : 0.f;
            }
        }

        float acc = a0 + a1;
        #pragma unroll
        for (int d = 16; d > 0; d >>= 1)
            acc += __shfl_down_sync(0xffffffffu, acc, d);
        if (lane == 0)
            ll += (unsigned long long)__float2ll_rn(acc * FXSCALE);
    }

    if (lane == 0 && ll) atomicAdd(&g_acc, ll);
    __threadfence();
    __syncthreads();

    if (tid == 0) {
        unsigned int done = atomicAdd(&g_count, 1u);
        if (done == PGRID - 1) {
            unsigned long long raw = atomicAdd(&g_acc, 0ULL);
            double sum = (double)(long long)raw * (1.0 / (double)FXSCALE);
            out[0] = (float)(10.0 * (2.0 * sum + (double)(NCHAIN * NPTS)));
            // reset for next graph replay (all blocks are past all reads)
            atomicExch(&g_acc, 0ULL);
            atomicExch(&g_count, 0u);
            atomicExch(&g_live_cnt, 0u);
            atomicExch(&g_ready, 0u);
        }
    }
}

extern "C" void kernel_launch(void* const* d_in, const int* in_sizes, int n_in,
                              void* d_out, int out_size) {
    const float* conf = (const float*)d_in[0];
    float* out = (float*)d_out;

    fused_kernel<<<PGRID, PBLOCK>>>(conf, out);
}

// round 10
// speedup vs baseline: 1.6404x; 1.6404x over previous
#include <cuda_runtime.h>

// Problem constants
#define NPTS     8193            // positions per chain (incl. leading zero row)
#define NCHAIN   2
#define CONFLEN  16388

// Chunking: 32-point tiles, one warp per tile pair
#define CHUNK    32
#define NCHUNK   257                             // ceil(8193/32)
#define PADN     (NCHUNK * CHUNK)                // 8224
#define NPAIR    (NCHUNK * (NCHUNK + 1) / 2)     // 33153 (cj >= ci)
#define MAXITEMS (NPAIR * NCHAIN)

#define SBLOCK   1024                            // setup block
#define PBLOCK   256                             // pair block
#define PGRID    592                             // pair grid
#define NWARPS   (PGRID * (PBLOCK / 32))         // 4736

// Scaled-space cutoff: dropped pair value <= 2^(-0.5*64) = 2.3e-10
#define DCUT_HAT 8.0f

// Fixed-point scale for deterministic integer accumulation
#define FXSCALE  16777216.0f     // 2^24

// Scratch (no allocations allowed; zero-initialized at load)
__device__ float4 g_pts[NCHAIN][PADN];           // (x_hat, y_hat, z_hat, a)
__device__ int    g_live[MAXITEMS];              // packed live items
__device__ unsigned int g_live_cnt;
__device__ unsigned long long g_acc;             // fixed-point sum
__device__ unsigned int g_count;                 // finished-block counter

// ---------------------------------------------------------------------------
// Setup + plan: one block per chain. Register-resident 8-steps-per-thread
// prefix sum, scaled points, 32-point chunk bounds, then cull all tile pairs
// into a compact live list (triangular index decoded once, walked after).
// ---------------------------------------------------------------------------
__global__ void __launch_bounds__(SBLOCK)
setup_kernel(const float* __restrict__ conf) {
    const int chain = blockIdx.x;
    const int tid = threadIdx.x;
    const int lane = tid & 31, warp = tid >> 5;
    const float2* cp = (const float2*)(conf + chain * CONFLEN + 4);
    const float TWO_PI = 6.2831853071795864769f;

    float px[8], py[8], pz[8];
    float sx = 0.f, sy = 0.f, sz = 0.f;
    #pragma unroll
    for (int m = 0; m < 8; m++) {
        float2 rr = cp[tid * 8 + m];
        float r1 = rr.x + 0.5f;
        float r2 = rr.y + 0.5f;
        float z  = 1.0f - 2.0f * r2;                   // cos(theta)
        float sth = sqrtf(fmaxf(1.0f - z * z, 0.0f));  // sin(theta)
        float s, c;
        __sincosf(r1 * TWO_PI, &s, &c);
        sx += sth * c;
        sy += sth * s;
        sz += z;
        px[m] = sx; py[m] = sy; pz[m] = sz;
    }

    // warp inclusive scan of thread totals
    float tx = sx, ty = sy, tz = sz;
    #pragma unroll
    for (int d = 1; d < 32; d <<= 1) {
        float ox = __shfl_up_sync(0xffffffffu, tx, d);
        float oy = __shfl_up_sync(0xffffffffu, ty, d);
        float oz = __shfl_up_sync(0xffffffffu, tz, d);
        if (lane >= d) { tx += ox; ty += oy; tz += oz; }
    }

    __shared__ float3 wtot[32], woff[32];
    __shared__ float4 lastpt_s;
    __shared__ float4 cb[NCHUNK];
    if (lane == 31) wtot[warp] = make_float3(tx, ty, tz);
    __syncthreads();
    if (tid == 0) {
        float ax = 0.f, ay = 0.f, az = 0.f;
        #pragma unroll
        for (int w = 0; w < 32; w++) {
            float3 v = wtot[w];
            woff[w] = make_float3(ax, ay, az);
            ax += v.x; ay += v.y; az += v.z;
        }
    }
    __syncthreads();
    float bx = woff[warp].x + (tx - sx);
    float by = woff[warp].y + (ty - sy);
    float bz = woff[warp].z + (tz - sz);

    // arg = a_i + a_j + dot(p_hat_i, p_hat_j), p_hat = SS*p, a=-0.5|p_hat|^2
    const float S2 = 8.0f * 1.4426950408889634f;   // 8*log2(e)
    const float SS = sqrtf(S2);                    // scaled step length

    float4 mylast = make_float4(0.f, 0.f, 0.f, 0.f);
    float mnx = 1e30f, mxx = -1e30f, mny = 1e30f, mxy = -1e30f;
    float mnz = 1e30f, mxz = -1e30f;
    #pragma unroll
    for (int m = 0; m < 8; m++) {
        float xh = SS * (bx + px[m]);
        float yh = SS * (by + py[m]);
        float zh = SS * (bz + pz[m]);
        float a = -0.5f * (xh * xh + yh * yh + zh * zh);
        mylast = make_float4(xh, yh, zh, a);
        g_pts[chain][tid * 8 + m + 1] = mylast;
        mnx = fminf(mnx, xh); mxx = fmaxf(mxx, xh);
        mny = fminf(mny, yh); mxy = fmaxf(mxy, yh);
        mnz = fminf(mnz, zh); mxz = fmaxf(mxz, zh);
    }
    if (tid == 0)    g_pts[chain][0] = make_float4(0.f, 0.f, 0.f, 0.f);
    if (tid == 1023) lastpt_s = mylast;   // point 8192

    // chunk bounds: threads 4c..4c+3 cover points [32c+1, 32c+33);
    // +SS inflation covers boundary point 32c.
    #pragma unroll
    for (int d = 1; d < 4; d <<= 1) {
        mnx = fminf(mnx, __shfl_xor_sync(0xffffffffu, mnx, d, 4));
        mxx = fmaxf(mxx, __shfl_xor_sync(0xffffffffu, mxx, d, 4));
        mny = fminf(mny, __shfl_xor_sync(0xffffffffu, mny, d, 4));
        mxy = fmaxf(mxy, __shfl_xor_sync(0xffffffffu, mxy, d, 4));
        mnz = fminf(mnz, __shfl_xor_sync(0xffffffffu, mnz, d, 4));
        mxz = fmaxf(mxz, __shfl_xor_sync(0xffffffffu, mxz, d, 4));
    }
    if ((tid & 3) == 0) {
        float hx = 0.5f * (mxx - mnx);
        float hy = 0.5f * (mxy - mny);
        float hz = 0.5f * (mxz - mnz);
        float r = sqrtf(hx * hx + hy * hy + hz * hz) + SS + 1e-2f;
        cb[tid >> 2] = make_float4(0.5f * (mnx + mxx), 0.5f * (mny + mxy),
                                   0.5f * (mnz + mxz), r);
    }
    __syncthreads();
    // chunk 256 = real point 8192 + 31 pads, all at lastpt
    if (tid == 0)
        cb[256] = make_float4(lastpt_s.x, lastpt_s.y, lastpt_s.z, 0.05f);
    // pads: a=-1e30 -> exp2 underflows to exactly 0
    if (tid < PADN - NPTS)
        g_pts[chain][NPTS + tid] =
            make_float4(lastpt_s.x, lastpt_s.y, lastpt_s.z, -1e30f);
    __syncthreads();

    // ---- plan: contiguous pair range per thread; decode start once, walk ----
    const int per = (NPAIR + SBLOCK - 1) / SBLOCK;       // 33
    int p0 = tid * per;
    int p1 = min(p0 + per, NPAIR);
    if (p0 < p1) {
        // decode p0 -> (ci, cj):  row offset S(ci) = ci*(2*NCHUNK+1-ci)/2
        float disc = (float)((2 * NCHUNK + 1) * (2 * NCHUNK + 1)) - 8.0f * (float)p0;
        int ci = (int)(((float)(2 * NCHUNK + 1) - sqrtf(disc)) * 0.5f);
        if (ci > NCHUNK - 1) ci = NCHUNK - 1;
        if (ci < 0) ci = 0;
        while (ci > 0 && (ci * (2 * NCHUNK + 1 - ci)) / 2 > p0) ci--;
        while (((ci + 1) * (2 * NCHUNK + 1 - (ci + 1))) / 2 <= p0) ci++;
        int cj = ci + (p0 - (ci * (2 * NCHUNK + 1 - ci)) / 2);

        for (int p = p0; p < p1; p++) {
            float4 bi = cb[ci];
            float4 bj = cb[cj];
            float dx = bi.x - bj.x, dy = bi.y - bj.y, dz = bi.z - bj.z;
            float rr = bi.w + bj.w + DCUT_HAT;
            if (dx * dx + dy * dy + dz * dz <= rr * rr) {
                unsigned int idx = atomicAdd(&g_live_cnt, 1u);
                g_live[idx] = (chain << 20) | (ci << 10) | cj;
            }
            if (++cj >= NCHUNK) { ci++; cj = ci; }
        }
    }
}

// ---------------------------------------------------------------------------
// Pair kernel: one warp per live tile pair (grid-stride). No intra-block
// sync at all. Per-item fixed-point quantization -> order-independent sum.
// Last block finalizes output and resets state for the next graph replay.
// ---------------------------------------------------------------------------
__global__ void __launch_bounds__(PBLOCK)
pair_kernel(float* __restrict__ out) {
    const int tid = threadIdx.x;
    const int lane = tid & 31;
    const unsigned int gw = blockIdx.x * (PBLOCK / 32) + (tid >> 5);

    const unsigned int nitems = g_live_cnt;
    unsigned long long ll = 0ULL;

    for (unsigned int it = gw; it < nitems; it += NWARPS) {
        const int item = g_live[it];
        const int chain = item >> 20;
        const int ci = (item >> 10) & 1023;
        const int cj = item & 1023;

        const float4* __restrict__ jp = &g_pts[chain][cj * CHUNK];
        float4 ip = g_pts[chain][ci * CHUNK + lane];
        float a0 = 0.f, a1 = 0.f;

        if (ci != cj) {
            #pragma unroll
            for (int jj = 0; jj < CHUNK; jj += 2) {
                float4 q0 = __ldg(&jp[jj]);
                float4 q1 = __ldg(&jp[jj + 1]);
                float m0 = fmaf(ip.x, q0.x, q0.w);
                m0 = fmaf(ip.y, q0.y, m0);
                m0 = fmaf(ip.z, q0.z, m0);
                float m1 = fmaf(ip.x, q1.x, q1.w);
                m1 = fmaf(ip.y, q1.y, m1);
                m1 = fmaf(ip.z, q1.z, m1);
                float e0, e1;
                asm("ex2.approx.f32 %0, %1;" : "=f"(e0) : "f"(m0 + ip.w));
                asm("ex2.approx.f32 %0, %1;" : "=f"(e1) : "f"(m1 + ip.w));
                a0 += e0;
                a1 += e1;
            }
        } else {
            #pragma unroll
            for (int jj = 0; jj < CHUNK; jj += 2) {
                float4 q0 = __ldg(&jp[jj]);
                float4 q1 = __ldg(&jp[jj + 1]);
                float m0 = fmaf(ip.x, q0.x, q0.w);
                m0 = fmaf(ip.y, q0.y, m0);
                m0 = fmaf(ip.z, q0.z, m0);
                float m1 = fmaf(ip.x, q1.x, q1.w);
                m1 = fmaf(ip.y, q1.y, m1);
                m1 = fmaf(ip.z, q1.z, m1);
                float e0, e1;
                asm("ex2.approx.f32 %0, %1;" : "=f"(e0) : "f"(m0 + ip.w));
                asm("ex2.approx.f32 %0, %1;" : "=f"(e1) : "f"(m1 + ip.w));
                a0 += (jj > lane) ? e0 : 0.f;        // strict upper triangle
                a1 += (jj + 1 > lane) ? e1 : 0.f;
            }
        }

        float acc = a0 + a1;
        #pragma unroll
        for (int d = 16; d > 0; d >>= 1)
            acc += __shfl_down_sync(0xffffffffu, acc, d);
        if (lane == 0)
            ll += (unsigned long long)__float2ll_rn(acc * FXSCALE);
    }

    if (lane == 0 && ll) atomicAdd(&g_acc, ll);
    __threadfence();
    __syncthreads();

    if (tid == 0) {
        unsigned int done = atomicAdd(&g_count, 1u);
        if (done == PGRID - 1) {
            unsigned long long raw = atomicAdd(&g_acc, 0ULL);
            double sum = (double)(long long)raw * (1.0 / (double)FXSCALE);
            out[0] = (float)(10.0 * (2.0 * sum + (double)(NCHAIN * NPTS)));
            // reset for next graph replay (all blocks are past all reads)
            atomicExch(&g_acc, 0ULL);
            atomicExch(&g_count, 0u);
            atomicExch(&g_live_cnt, 0u);
        }
    }
}

extern "C" void kernel_launch(void* const* d_in, const int* in_sizes, int n_in,
                              void* d_out, int out_size) {
    const float* conf = (const float*)d_in[0];
    float* out = (float*)d_out;

    setup_kernel<<<NCHAIN, SBLOCK>>>(conf);
    pair_kernel<<<PGRID, PBLOCK>>>(out);
}